// round 3
// baseline (speedup 1.0000x reference)
#include <cuda_runtime.h>
#include <cstdint>

#define NTOK 1024
#define NHEAD 20003
#define HCH 20        // head vocab chunks
#define HROWS 1024    // rows per head chunk

// ---------------- scratch (device globals; no allocs allowed) ----------------
__device__ float g_hp0[NTOK * 512];
__device__ float g_hp1[NTOK * 128];
__device__ float g_hp2[NTOK * 32];
__device__ float g_hp3[NTOK * 8];
__device__ float g_ph[32 * HCH * 32];      // head partial sumexp [tile][chunk][lane]
__device__ float g_nh[NTOK];               // head needed logit per token
__device__ float g_pt[3][32 * 40 * 32];    // tail partial sumexp per cluster
__device__ float g_nt[NTOK];               // tail target logit per token
__device__ int   g_cid[NTOK];
__device__ int   g_pos[NTOK];
__device__ int   g_list[3][NTOK];
__device__ int   g_cnt[3];

// ---------------- f32x2 packed FMA helpers (sm_103a) ----------------
__device__ __forceinline__ unsigned long long ffma2(unsigned long long a,
                                                    unsigned long long b,
                                                    unsigned long long c) {
    unsigned long long d;
    asm("fma.rn.f32x2 %0, %1, %2, %3;" : "=l"(d) : "l"(a), "l"(b), "l"(c));
    return d;
}
__device__ __forceinline__ float f2lo(unsigned long long v) {
    return __uint_as_float((unsigned)v);
}
__device__ __forceinline__ float f2hi(unsigned long long v) {
    return __uint_as_float((unsigned)(v >> 32));
}

// ---------------- 1) projections: hp_i = hidden @ proj_i ----------------
__global__ void k_proj(const float* __restrict__ hidden,
                       const float* __restrict__ p0, const float* __restrict__ p1,
                       const float* __restrict__ p2, const float* __restrict__ p3) {
    __shared__ float h[512];
    int t = blockIdx.x;
    for (int k = threadIdx.x; k < 512; k += blockDim.x) h[k] = hidden[t * 512 + k];
    __syncthreads();
    for (int j = threadIdx.x; j < 512; j += 256) {
        float s = 0.f;
#pragma unroll 8
        for (int k = 0; k < 512; k++) s = fmaf(h[k], p0[k * 512 + j], s);
        g_hp0[t * 512 + j] = s;
    }
    if (threadIdx.x < 128) {
        int j = threadIdx.x; float s = 0.f;
#pragma unroll 8
        for (int k = 0; k < 512; k++) s = fmaf(h[k], p1[k * 128 + j], s);
        g_hp1[t * 128 + j] = s;
    }
    if (threadIdx.x < 32) {
        int j = threadIdx.x; float s = 0.f;
#pragma unroll 8
        for (int k = 0; k < 512; k++) s = fmaf(h[k], p2[k * 32 + j], s);
        g_hp2[t * 32 + j] = s;
    }
    if (threadIdx.x < 8) {
        int j = threadIdx.x; float s = 0.f;
#pragma unroll 8
        for (int k = 0; k < 512; k++) s = fmaf(h[k], p3[k * 8 + j], s);
        g_hp3[t * 8 + j] = s;
    }
}

// ---------------- 2) cluster-id + compaction ----------------
__global__ void k_compact(const int* __restrict__ target) {
    int t = threadIdx.x;
    if (t < 3) g_cnt[t] = 0;
    __syncthreads();
    int tg = target[t];
    int cid = (tg >= 20000) + (tg >= 40000) + (tg >= 200000);
    g_cid[t] = cid;
    if (cid > 0) {
        int p = atomicAdd(&g_cnt[cid - 1], 1);
        g_list[cid - 1][p] = t;
        g_pos[t] = p;
    } else {
        g_pos[t] = -1;
    }
}

// ---------------- 3) head: fused GEMM + online sumexp + needed-logit gather ----
extern __shared__ float sdyn[];
__global__ void __launch_bounds__(256)
k_head(const float* __restrict__ W0, const float* __restrict__ b0,
       const float* __restrict__ CW, const float* __restrict__ CB,
       const int* __restrict__ target) {
    float* sh  = sdyn;             // (512/2) * 66 floats, pair-interleaved hp0 tile
    float* red = sdyn + 256 * 66;  // 512 floats for cross-warp reduce
    int tile = blockIdx.x, chunk = blockIdx.y;
    int tid = threadIdx.x, warp = tid >> 5, lane = tid & 31;

    // stage hp0 tile transposed + pair-interleaved: sh[(k/2)*66 + 2*t + (k&1)]
    for (int idx = tid; idx < 32 * 512; idx += 256) {
        int t = idx >> 9, k = idx & 511;
        sh[(k >> 1) * 66 + (t << 1) + (k & 1)] = g_hp0[(tile * 32 + t) * 512 + k];
    }
    __syncthreads();

    int token = tile * 32 + lane;
    int tg = target[token];
    int cid = (tg >= 20000) + (tg >= 40000) + (tg >= 200000);
    int needcol = cid ? (NHEAD - cid) : tg;

    float s = 0.f, need = 0.f;
    int cs = chunk * HROWS;
    int ce = min(cs + HROWS, NHEAD);

    for (int r = cs + warp * 4; r < ce; r += 32) {
        int rr1 = (r + 1 < ce) ? r + 1 : cs;
        int rr2 = (r + 2 < ce) ? r + 2 : cs;
        int rr3 = (r + 3 < ce) ? r + 3 : cs;
        const float* wp0 = (r   < 20000) ? W0 + (size_t)r   * 512 : CW + (size_t)(r   - 20000) * 512;
        const float* wp1 = (rr1 < 20000) ? W0 + (size_t)rr1 * 512 : CW + (size_t)(rr1 - 20000) * 512;
        const float* wp2 = (rr2 < 20000) ? W0 + (size_t)rr2 * 512 : CW + (size_t)(rr2 - 20000) * 512;
        const float* wp3 = (rr3 < 20000) ? W0 + (size_t)rr3 * 512 : CW + (size_t)(rr3 - 20000) * 512;
        float bb0 = (r   < 20000) ? b0[r]   : CB[r   - 20000];
        float bb1 = (rr1 < 20000) ? b0[rr1] : CB[rr1 - 20000];
        float bb2 = (rr2 < 20000) ? b0[rr2] : CB[rr2 - 20000];
        float bb3 = (rr3 < 20000) ? b0[rr3] : CB[rr3 - 20000];

        unsigned long long acc0 = 0ull, acc1 = 0ull, acc2 = 0ull, acc3 = 0ull;
#pragma unroll 8
        for (int k = 0; k < 512; k += 4) {
            const float* abase = sh + (k >> 1) * 66 + (lane << 1);
            unsigned long long a01 = *(const unsigned long long*)(abase);
            unsigned long long a23 = *(const unsigned long long*)(abase + 66);
            ulonglong2 w0 = *(const ulonglong2*)(wp0 + k);
            ulonglong2 w1 = *(const ulonglong2*)(wp1 + k);
            ulonglong2 w2 = *(const ulonglong2*)(wp2 + k);
            ulonglong2 w3 = *(const ulonglong2*)(wp3 + k);
            acc0 = ffma2(a01, w0.x, acc0); acc0 = ffma2(a23, w0.y, acc0);
            acc1 = ffma2(a01, w1.x, acc1); acc1 = ffma2(a23, w1.y, acc1);
            acc2 = ffma2(a01, w2.x, acc2); acc2 = ffma2(a23, w2.y, acc2);
            acc3 = ffma2(a01, w3.x, acc3); acc3 = ffma2(a23, w3.y, acc3);
        }
        {
            float lg = f2lo(acc0) + f2hi(acc0) + bb0;
            s += __expf(lg); if (r == needcol) need = lg;
        }
        if (r + 1 < ce) {
            float lg = f2lo(acc1) + f2hi(acc1) + bb1;
            s += __expf(lg); if (r + 1 == needcol) need = lg;
        }
        if (r + 2 < ce) {
            float lg = f2lo(acc2) + f2hi(acc2) + bb2;
            s += __expf(lg); if (r + 2 == needcol) need = lg;
        }
        if (r + 3 < ce) {
            float lg = f2lo(acc3) + f2hi(acc3) + bb3;
            s += __expf(lg); if (r + 3 == needcol) need = lg;
        }
    }

    red[tid] = s;
    red[256 + tid] = need;
    __syncthreads();
    if (warp == 0) {
        float ts = 0.f, tn = 0.f;
#pragma unroll
        for (int w = 0; w < 8; w++) { ts += red[w * 32 + lane]; tn += red[256 + w * 32 + lane]; }
        g_ph[(tile * HCH + chunk) * 32 + lane] = ts;
        if (needcol >= cs && needcol < ce) g_nh[token] = tn;
    }
}

// ---------------- 4) tails: same fused structure on compacted token lists -----
template <int E, int CH, int CROWS>
__global__ void __launch_bounds__(256)
k_tail(const float* __restrict__ W, const float* __restrict__ b,
       int V, int L, int c, const int* __restrict__ target) {
    __shared__ float sh[(E / 2) * 66];
    __shared__ float red[512];
    const float* hp = (E == 128) ? g_hp1 : (E == 32) ? g_hp2 : g_hp3;
    int cnt = g_cnt[c];
    int tile = blockIdx.x;
    if (tile * 32 >= cnt) return;
    int chunk = blockIdx.y;
    int tid = threadIdx.x, warp = tid >> 5, lane = tid & 31;

    for (int idx = tid; idx < 32 * E; idx += 256) {
        int t = idx / E, k = idx % E;
        int gp = tile * 32 + t;
        int token = (gp < cnt) ? g_list[c][gp] : g_list[c][0];
        sh[(k >> 1) * 66 + (t << 1) + (k & 1)] = hp[token * E + k];
    }
    __syncthreads();

    int gp = tile * 32 + lane;
    bool active = gp < cnt;
    int token = active ? g_list[c][gp] : g_list[c][0];
    int rel = target[token] - L;
    rel = max(0, min(rel, V - 1));

    float s = 0.f, need = 0.f;
    int cs = chunk * CROWS;
    int ce = min(cs + CROWS, V);

    for (int r = cs + warp * 4; r < ce; r += 32) {
        int rr1 = (r + 1 < ce) ? r + 1 : cs;
        int rr2 = (r + 2 < ce) ? r + 2 : cs;
        int rr3 = (r + 3 < ce) ? r + 3 : cs;
        const float* wp0 = W + (size_t)r   * E;
        const float* wp1 = W + (size_t)rr1 * E;
        const float* wp2 = W + (size_t)rr2 * E;
        const float* wp3 = W + (size_t)rr3 * E;
        unsigned long long acc0 = 0ull, acc1 = 0ull, acc2 = 0ull, acc3 = 0ull;
#pragma unroll
        for (int k = 0; k < E; k += 4) {
            const float* abase = sh + (k >> 1) * 66 + (lane << 1);
            unsigned long long a01 = *(const unsigned long long*)(abase);
            unsigned long long a23 = *(const unsigned long long*)(abase + 66);
            ulonglong2 w0 = *(const ulonglong2*)(wp0 + k);
            ulonglong2 w1 = *(const ulonglong2*)(wp1 + k);
            ulonglong2 w2 = *(const ulonglong2*)(wp2 + k);
            ulonglong2 w3 = *(const ulonglong2*)(wp3 + k);
            acc0 = ffma2(a01, w0.x, acc0); acc0 = ffma2(a23, w0.y, acc0);
            acc1 = ffma2(a01, w1.x, acc1); acc1 = ffma2(a23, w1.y, acc1);
            acc2 = ffma2(a01, w2.x, acc2); acc2 = ffma2(a23, w2.y, acc2);
            acc3 = ffma2(a01, w3.x, acc3); acc3 = ffma2(a23, w3.y, acc3);
        }
        {
            float lg = f2lo(acc0) + f2hi(acc0) + b[r];
            s += __expf(lg); if (r == rel) need = lg;
        }
        if (r + 1 < ce) {
            float lg = f2lo(acc1) + f2hi(acc1) + b[r + 1];
            s += __expf(lg); if (r + 1 == rel) need = lg;
        }
        if (r + 2 < ce) {
            float lg = f2lo(acc2) + f2hi(acc2) + b[r + 2];
            s += __expf(lg); if (r + 2 == rel) need = lg;
        }
        if (r + 3 < ce) {
            float lg = f2lo(acc3) + f2hi(acc3) + b[r + 3];
            s += __expf(lg); if (r + 3 == rel) need = lg;
        }
    }

    red[tid] = s;
    red[256 + tid] = need;
    __syncthreads();
    if (warp == 0) {
        float ts = 0.f, tn = 0.f;
#pragma unroll
        for (int w = 0; w < 8; w++) { ts += red[w * 32 + lane]; tn += red[256 + w * 32 + lane]; }
        g_pt[c][(tile * CH + chunk) * 32 + lane] = ts;
        if (active && rel >= cs && rel < ce) g_nt[token] = tn;
    }
}

// ---------------- 5) combine partials -> nll ----------------
__global__ void k_comb(float* __restrict__ out) {
    int t = blockIdx.x * 256 + threadIdx.x;
    if (t >= NTOK) return;
    int tile = t >> 5, lane = t & 31;
    float s = 0.f;
#pragma unroll
    for (int c = 0; c < HCH; c++) s += g_ph[(tile * HCH + c) * 32 + lane];
    float hl = g_nh[t] - logf(s);
    float nll = -hl;
    int cid = g_cid[t];
    if (cid > 0) {
        int p = g_pos[t];
        int CH = (cid == 1) ? 10 : (cid == 2) ? 40 : 20;
        int pt = p >> 5, pl = p & 31;
        float st = 0.f;
        for (int c = 0; c < CH; c++) st += g_pt[cid - 1][(pt * CH + c) * 32 + pl];
        nll = -(hl + g_nt[t] - logf(st));
    }
    out[t] = nll;
}

// ---------------- launch ----------------
extern "C" void kernel_launch(void* const* d_in, const int* in_sizes, int n_in,
                              void* d_out, int out_size) {
    const float* hidden = (const float*)d_in[0];
    const int*   target = (const int*)d_in[1];
    const float* W0 = (const float*)d_in[2];
    const float* b0 = (const float*)d_in[3];
    const float* p0 = (const float*)d_in[4];
    const float* W1 = (const float*)d_in[5];
    const float* b1 = (const float*)d_in[6];
    const float* p1 = (const float*)d_in[7];
    const float* W2 = (const float*)d_in[8];
    const float* b2 = (const float*)d_in[9];
    const float* p2 = (const float*)d_in[10];
    const float* W3 = (const float*)d_in[11];
    const float* b3 = (const float*)d_in[12];
    const float* p3 = (const float*)d_in[13];
    const float* CW = (const float*)d_in[14];
    const float* CB = (const float*)d_in[15];

    size_t shb = (size_t)(256 * 66 + 512) * sizeof(float);  // 69632 B
    cudaFuncSetAttribute(k_head, cudaFuncAttributeMaxDynamicSharedMemorySize, (int)shb);

    k_proj<<<NTOK, 256>>>(hidden, p0, p1, p2, p3);
    k_compact<<<1, NTOK>>>(target);
    k_head<<<dim3(32, HCH), 256, shb>>>(W0, b0, CW, CB, target);
    k_tail<128, 10, 2048><<<dim3(32, 10), 256>>>(W1, b1, 20000, 20000, 0, target);
    k_tail<32,  40, 4096><<<dim3(32, 40), 256>>>(W2, b2, 160000, 40000, 1, target);
    k_tail<8,   20, 3392><<<dim3(32, 20), 256>>>(W3, b3, 67735, 200000, 2, target);
    k_comb<<<4, 256>>>((float*)d_out);
}

// round 5
// speedup vs baseline: 1.3450x; 1.3450x over previous
#include <cuda_runtime.h>
#include <cstdint>

#define NTOK 1024
#define NHEAD 20003
#define HCH 40        // head vocab chunks
#define HROWS 512     // rows per head chunk
#define CH1 79        // tail1 chunks (CROWS 256)
#define CH2 157       // tail2 chunks (CROWS 1024)
#define CH3 133       // tail3 chunks (CROWS 512)

// ---------------- scratch (device globals; no allocs allowed) ----------------
__device__ float g_hp0[NTOK * 512];
__device__ float g_hp1[NTOK * 128];
__device__ float g_hp2[NTOK * 32];
__device__ float g_hp3[NTOK * 8];
__device__ float g_ph[32 * HCH * 32];       // head partial sumexp [tile][chunk][lane]
__device__ float g_nh[NTOK];                // head needed logit per token
__device__ float g_pt[3][32 * 160 * 32];    // tail partial sumexp per cluster
__device__ float g_nt[NTOK];                // tail target logit per token
__device__ int   g_cid[NTOK];
__device__ int   g_pos[NTOK];
__device__ int   g_list[3][NTOK];
__device__ int   g_cnt[3];

// ---------------- f32x2 packed FMA helpers (sm_103a) ----------------
__device__ __forceinline__ unsigned long long ffma2(unsigned long long a,
                                                    unsigned long long b,
                                                    unsigned long long c) {
    unsigned long long d;
    asm("fma.rn.f32x2 %0, %1, %2, %3;" : "=l"(d) : "l"(a), "l"(b), "l"(c));
    return d;
}
__device__ __forceinline__ float f2lo(unsigned long long v) {
    return __uint_as_float((unsigned)v);
}
__device__ __forceinline__ float f2hi(unsigned long long v) {
    return __uint_as_float((unsigned)(v >> 32));
}

// ---------------- 1) projections: hp_i = hidden @ proj_i (8-token tiles) -----
__global__ void __launch_bounds__(512)
k_proj(const float* __restrict__ hidden,
       const float* __restrict__ p0, const float* __restrict__ p1,
       const float* __restrict__ p2, const float* __restrict__ p3) {
    __shared__ float h[8][512];
    int t0 = blockIdx.x * 8;
    int tid = threadIdx.x;
    for (int i = tid; i < 8 * 512; i += 512)
        h[i >> 9][i & 511] = hidden[(t0 + (i >> 9)) * 512 + (i & 511)];
    __syncthreads();
    {
        int j = tid;
        float a[8];
#pragma unroll
        for (int i = 0; i < 8; i++) a[i] = 0.f;
#pragma unroll 4
        for (int k = 0; k < 512; k++) {
            float w = p0[k * 512 + j];
#pragma unroll
            for (int i = 0; i < 8; i++) a[i] = fmaf(h[i][k], w, a[i]);
        }
#pragma unroll
        for (int i = 0; i < 8; i++) g_hp0[(t0 + i) * 512 + j] = a[i];
    }
    if (tid < 128) {
        int j = tid;
        float a[8];
#pragma unroll
        for (int i = 0; i < 8; i++) a[i] = 0.f;
#pragma unroll 4
        for (int k = 0; k < 512; k++) {
            float w = p1[k * 128 + j];
#pragma unroll
            for (int i = 0; i < 8; i++) a[i] = fmaf(h[i][k], w, a[i]);
        }
#pragma unroll
        for (int i = 0; i < 8; i++) g_hp1[(t0 + i) * 128 + j] = a[i];
    }
    if (tid < 32) {
        int j = tid;
        float a[8];
#pragma unroll
        for (int i = 0; i < 8; i++) a[i] = 0.f;
#pragma unroll 4
        for (int k = 0; k < 512; k++) {
            float w = p2[k * 32 + j];
#pragma unroll
            for (int i = 0; i < 8; i++) a[i] = fmaf(h[i][k], w, a[i]);
        }
#pragma unroll
        for (int i = 0; i < 8; i++) g_hp2[(t0 + i) * 32 + j] = a[i];
    }
    if (tid < 8) {
        int j = tid;
        float a[8];
#pragma unroll
        for (int i = 0; i < 8; i++) a[i] = 0.f;
#pragma unroll 4
        for (int k = 0; k < 512; k++) {
            float w = p3[k * 8 + j];
#pragma unroll
            for (int i = 0; i < 8; i++) a[i] = fmaf(h[i][k], w, a[i]);
        }
#pragma unroll
        for (int i = 0; i < 8; i++) g_hp3[(t0 + i) * 8 + j] = a[i];
    }
}

// ---------------- 2) cluster-id + compaction ----------------
__global__ void k_compact(const int* __restrict__ target) {
    int t = threadIdx.x;
    if (t < 3) g_cnt[t] = 0;
    __syncthreads();
    int tg = target[t];
    int cid = (tg >= 20000) + (tg >= 40000) + (tg >= 200000);
    g_cid[t] = cid;
    if (cid > 0) {
        int p = atomicAdd(&g_cnt[cid - 1], 1);
        g_list[cid - 1][p] = t;
        g_pos[t] = p;
    } else {
        g_pos[t] = -1;
    }
}

// ---------------- 3) head: fused GEMM + online sumexp + needed-logit gather ---
extern __shared__ float sdyn[];
__global__ void __launch_bounds__(128, 3)
k_head(const float* __restrict__ W0, const float* __restrict__ b0,
       const float* __restrict__ CW, const float* __restrict__ CB,
       const int* __restrict__ target) {
    float* sh  = sdyn;             // (512/2) * 66 floats, pair-interleaved hp0 tile
    float* red = sdyn + 256 * 66;  // 256 floats for cross-warp reduce
    int tile = blockIdx.x, chunk = blockIdx.y;
    int tid = threadIdx.x, warp = tid >> 5, lane = tid & 31;

    // stage hp0 tile transposed + pair-interleaved: sh[(k/2)*66 + 2*t + (k&1)]
    for (int idx = tid; idx < 32 * 512; idx += 128) {
        int t = idx >> 9, k = idx & 511;
        sh[(k >> 1) * 66 + (t << 1) + (k & 1)] = g_hp0[(tile * 32 + t) * 512 + k];
    }
    __syncthreads();

    int token = tile * 32 + lane;
    int tg = target[token];
    int cid = (tg >= 20000) + (tg >= 40000) + (tg >= 200000);
    int needcol = cid ? (NHEAD - cid) : tg;

    float s = 0.f, need = 0.f;
    int cs = chunk * HROWS;
    int ce = min(cs + HROWS, NHEAD);

    for (int r = cs + warp * 4; r < ce; r += 16) {
        int rr1 = (r + 1 < ce) ? r + 1 : cs;
        int rr2 = (r + 2 < ce) ? r + 2 : cs;
        int rr3 = (r + 3 < ce) ? r + 3 : cs;
        const float* wp0 = (r   < 20000) ? W0 + (size_t)r   * 512 : CW + (size_t)(r   - 20000) * 512;
        const float* wp1 = (rr1 < 20000) ? W0 + (size_t)rr1 * 512 : CW + (size_t)(rr1 - 20000) * 512;
        const float* wp2 = (rr2 < 20000) ? W0 + (size_t)rr2 * 512 : CW + (size_t)(rr2 - 20000) * 512;
        const float* wp3 = (rr3 < 20000) ? W0 + (size_t)rr3 * 512 : CW + (size_t)(rr3 - 20000) * 512;
        float bb0 = (r   < 20000) ? b0[r]   : CB[r   - 20000];
        float bb1 = (rr1 < 20000) ? b0[rr1] : CB[rr1 - 20000];
        float bb2 = (rr2 < 20000) ? b0[rr2] : CB[rr2 - 20000];
        float bb3 = (rr3 < 20000) ? b0[rr3] : CB[rr3 - 20000];

        unsigned long long acc0 = 0ull, acc1 = 0ull, acc2 = 0ull, acc3 = 0ull;
#pragma unroll 8
        for (int k = 0; k < 512; k += 4) {
            const float* abase = sh + (k >> 1) * 66 + (lane << 1);
            unsigned long long a01 = *(const unsigned long long*)(abase);
            unsigned long long a23 = *(const unsigned long long*)(abase + 66);
            ulonglong2 w0 = *(const ulonglong2*)(wp0 + k);
            ulonglong2 w1 = *(const ulonglong2*)(wp1 + k);
            ulonglong2 w2 = *(const ulonglong2*)(wp2 + k);
            ulonglong2 w3 = *(const ulonglong2*)(wp3 + k);
            acc0 = ffma2(a01, w0.x, acc0); acc0 = ffma2(a23, w0.y, acc0);
            acc1 = ffma2(a01, w1.x, acc1); acc1 = ffma2(a23, w1.y, acc1);
            acc2 = ffma2(a01, w2.x, acc2); acc2 = ffma2(a23, w2.y, acc2);
            acc3 = ffma2(a01, w3.x, acc3); acc3 = ffma2(a23, w3.y, acc3);
        }
        {
            float lg = f2lo(acc0) + f2hi(acc0) + bb0;
            s += __expf(lg); if (r == needcol) need = lg;
        }
        if (r + 1 < ce) {
            float lg = f2lo(acc1) + f2hi(acc1) + bb1;
            s += __expf(lg); if (r + 1 == needcol) need = lg;
        }
        if (r + 2 < ce) {
            float lg = f2lo(acc2) + f2hi(acc2) + bb2;
            s += __expf(lg); if (r + 2 == needcol) need = lg;
        }
        if (r + 3 < ce) {
            float lg = f2lo(acc3) + f2hi(acc3) + bb3;
            s += __expf(lg); if (r + 3 == needcol) need = lg;
        }
    }

    red[tid] = s;
    red[128 + tid] = need;
    __syncthreads();
    if (warp == 0) {
        float ts = red[lane] + red[32 + lane] + red[64 + lane] + red[96 + lane];
        float tn = red[128 + lane] + red[160 + lane] + red[192 + lane] + red[224 + lane];
        g_ph[(tile * HCH + chunk) * 32 + lane] = ts;
        if (needcol >= cs && needcol < ce) g_nh[token] = tn;
    }
}

// ---------------- 4) tails: same fused structure on compacted token lists -----
template <int E, int CH, int CROWS>
__global__ void __launch_bounds__(128, 3)
k_tail(const float* __restrict__ W, const float* __restrict__ b,
       int V, int L, int c, const int* __restrict__ target) {
    __shared__ float sh[(E / 2) * 66];
    __shared__ float red[256];
    const float* hp = (E == 128) ? g_hp1 : (E == 32) ? g_hp2 : g_hp3;
    int cnt = g_cnt[c];
    int tile = blockIdx.x;
    if (tile * 32 >= cnt) return;
    int chunk = blockIdx.y;
    int tid = threadIdx.x, warp = tid >> 5, lane = tid & 31;

    for (int idx = tid; idx < 32 * E; idx += 128) {
        int t = idx / E, k = idx % E;
        int gp = tile * 32 + t;
        int token = (gp < cnt) ? g_list[c][gp] : g_list[c][0];
        sh[(k >> 1) * 66 + (t << 1) + (k & 1)] = hp[token * E + k];
    }
    __syncthreads();

    int gp = tile * 32 + lane;
    bool active = gp < cnt;
    int token = active ? g_list[c][gp] : g_list[c][0];
    int rel = target[token] - L;
    rel = max(0, min(rel, V - 1));

    float s = 0.f, need = 0.f;
    int cs = chunk * CROWS;
    int ce = min(cs + CROWS, V);

    for (int r = cs + warp * 4; r < ce; r += 16) {
        int rr1 = (r + 1 < ce) ? r + 1 : cs;
        int rr2 = (r + 2 < ce) ? r + 2 : cs;
        int rr3 = (r + 3 < ce) ? r + 3 : cs;
        const float* wp0 = W + (size_t)r   * E;
        const float* wp1 = W + (size_t)rr1 * E;
        const float* wp2 = W + (size_t)rr2 * E;
        const float* wp3 = W + (size_t)rr3 * E;
        unsigned long long acc0 = 0ull, acc1 = 0ull, acc2 = 0ull, acc3 = 0ull;
#pragma unroll
        for (int k = 0; k < E; k += 4) {
            const float* abase = sh + (k >> 1) * 66 + (lane << 1);
            unsigned long long a01 = *(const unsigned long long*)(abase);
            unsigned long long a23 = *(const unsigned long long*)(abase + 66);
            ulonglong2 w0 = *(const ulonglong2*)(wp0 + k);
            ulonglong2 w1 = *(const ulonglong2*)(wp1 + k);
            ulonglong2 w2 = *(const ulonglong2*)(wp2 + k);
            ulonglong2 w3 = *(const ulonglong2*)(wp3 + k);
            acc0 = ffma2(a01, w0.x, acc0); acc0 = ffma2(a23, w0.y, acc0);
            acc1 = ffma2(a01, w1.x, acc1); acc1 = ffma2(a23, w1.y, acc1);
            acc2 = ffma2(a01, w2.x, acc2); acc2 = ffma2(a23, w2.y, acc2);
            acc3 = ffma2(a01, w3.x, acc3); acc3 = ffma2(a23, w3.y, acc3);
        }
        {
            float lg = f2lo(acc0) + f2hi(acc0) + b[r];
            s += __expf(lg); if (r == rel) need = lg;
        }
        if (r + 1 < ce) {
            float lg = f2lo(acc1) + f2hi(acc1) + b[r + 1];
            s += __expf(lg); if (r + 1 == rel) need = lg;
        }
        if (r + 2 < ce) {
            float lg = f2lo(acc2) + f2hi(acc2) + b[r + 2];
            s += __expf(lg); if (r + 2 == rel) need = lg;
        }
        if (r + 3 < ce) {
            float lg = f2lo(acc3) + f2hi(acc3) + b[r + 3];
            s += __expf(lg); if (r + 3 == rel) need = lg;
        }
    }

    red[tid] = s;
    red[128 + tid] = need;
    __syncthreads();
    if (warp == 0) {
        float ts = red[lane] + red[32 + lane] + red[64 + lane] + red[96 + lane];
        float tn = red[128 + lane] + red[160 + lane] + red[192 + lane] + red[224 + lane];
        g_pt[c][(tile * CH + chunk) * 32 + lane] = ts;
        if (active && rel >= cs && rel < ce) g_nt[token] = tn;
    }
}

// ---------------- 5) combine partials -> nll ----------------
__global__ void k_comb(float* __restrict__ out) {
    int t = blockIdx.x * 256 + threadIdx.x;
    if (t >= NTOK) return;
    int tile = t >> 5, lane = t & 31;
    float s = 0.f;
#pragma unroll
    for (int c = 0; c < HCH; c++) s += g_ph[(tile * HCH + c) * 32 + lane];
    float hl = g_nh[t] - logf(s);
    float nll = -hl;
    int cid = g_cid[t];
    if (cid > 0) {
        int p = g_pos[t];
        int CH = (cid == 1) ? CH1 : (cid == 2) ? CH2 : CH3;
        int pt = p >> 5, pl = p & 31;
        float st = 0.f;
        for (int c = 0; c < CH; c++) st += g_pt[cid - 1][(pt * CH + c) * 32 + pl];
        nll = -(hl + g_nt[t] - logf(st));
    }
    out[t] = nll;
}

// ---------------- launch ----------------
extern "C" void kernel_launch(void* const* d_in, const int* in_sizes, int n_in,
                              void* d_out, int out_size) {
    const float* hidden = (const float*)d_in[0];
    const int*   target = (const int*)d_in[1];
    const float* W0 = (const float*)d_in[2];
    const float* b0 = (const float*)d_in[3];
    const float* p0 = (const float*)d_in[4];
    const float* W1 = (const float*)d_in[5];
    const float* b1 = (const float*)d_in[6];
    const float* p1 = (const float*)d_in[7];
    const float* W2 = (const float*)d_in[8];
    const float* b2 = (const float*)d_in[9];
    const float* p2 = (const float*)d_in[10];
    const float* W3 = (const float*)d_in[11];
    const float* b3 = (const float*)d_in[12];
    const float* p3 = (const float*)d_in[13];
    const float* CW = (const float*)d_in[14];
    const float* CB = (const float*)d_in[15];

    size_t shb = (size_t)(256 * 66 + 256) * sizeof(float);  // 68608 B
    cudaFuncSetAttribute(k_head, cudaFuncAttributeMaxDynamicSharedMemorySize, (int)shb);

    k_proj<<<NTOK / 8, 512>>>(hidden, p0, p1, p2, p3);
    k_compact<<<1, NTOK>>>(target);
    k_head<<<dim3(32, HCH), 128, shb>>>(W0, b0, CW, CB, target);
    k_tail<128, CH1, 256 ><<<dim3(32, CH1), 128>>>(W1, b1, 20000, 20000, 0, target);
    k_tail<32,  CH2, 1024><<<dim3(32, CH2), 128>>>(W2, b2, 160000, 40000, 1, target);
    k_tail<8,   CH3, 512 ><<<dim3(32, CH3), 128>>>(W3, b3, 67735, 200000, 2, target);
    k_comb<<<4, 256>>>((float*)d_out);
}

// round 6
// speedup vs baseline: 2.2136x; 1.6458x over previous
#include <cuda_runtime.h>
#include <cstdint>

#define NTOK 1024
#define NHEAD 20003
#define HCHUNKS 626          // head row chunks of 32 (20032 rows padded)
#define NCH1 625             // tail1: 20000 / 32
#define NCH2 2500            // tail2: 160000 / 64
#define NCH3 2117            // tail3: ceil(67735/32), padded to 67744
#define V3PAD (NCH3 * 32)
#define TILES1 2
#define TILES2 11
#define TILES3 6

// ---------------- scratch (device globals; no allocs) ----------------
__device__ __align__(256) float g_headW[20032 * 512];   // W0 ++ CW ++ zero pad
__device__ __align__(256) float g_headB[20032];
__device__ __align__(256) float g_W3p[V3PAD * 8];
__device__ __align__(256) float g_b3p[V3PAD];
__device__ __align__(256) float g_hp0[NTOK * 512];
__device__ __align__(256) float g_hp1[NTOK * 128];
__device__ __align__(256) float g_hp2[NTOK * 32];
__device__ __align__(256) float g_hp3[NTOK * 8];
__device__ float g_ph[NTOK * HCHUNKS];
__device__ float g_nh[NTOK];
__device__ float g_nt[NTOK];
__device__ float g_pt1[TILES1 * 64 * NCH1];
__device__ float g_pt2[TILES2 * 64 * NCH2];
__device__ float g_pt3[TILES3 * 64 * NCH3];
__device__ int   g_pos[NTOK];
__device__ int   g_list[3][NTOK];
__device__ int   g_cnt[3];

// ---------------- f32x2 helpers ----------------
__device__ __forceinline__ unsigned long long ffma2(unsigned long long a,
                                                    unsigned long long b,
                                                    unsigned long long c) {
    unsigned long long d;
    asm("fma.rn.f32x2 %0, %1, %2, %3;" : "=l"(d) : "l"(a), "l"(b), "l"(c));
    return d;
}
__device__ __forceinline__ float f2lo(unsigned long long v) { return __uint_as_float((unsigned)v); }
__device__ __forceinline__ float f2hi(unsigned long long v) { return __uint_as_float((unsigned)(v >> 32)); }

// ---------------- 0) prep: pack head weights, pad W3 ----------------
__global__ void k_prep(const float4* __restrict__ W0, const float* __restrict__ b0,
                       const float4* __restrict__ CW, const float* __restrict__ CB,
                       const float4* __restrict__ W3, const float* __restrict__ b3) {
    int i = blockIdx.x * 256 + threadIdx.x;
    int stride = gridDim.x * 256;
    float4 z = make_float4(0.f, 0.f, 0.f, 0.f);
    float4* HW = (float4*)g_headW;
    for (int idx = i; idx < 20032 * 128; idx += stride) {
        float4 v = z;
        if (idx < 20000 * 128) v = W0[idx];
        else if (idx < NHEAD * 128) v = CW[idx - 20000 * 128];
        HW[idx] = v;
    }
    float4* W3P = (float4*)g_W3p;
    for (int idx = i; idx < V3PAD * 2; idx += stride)
        W3P[idx] = (idx < 67735 * 2) ? W3[idx] : z;
    for (int idx = i; idx < 20032; idx += stride)
        g_headB[idx] = (idx < 20000) ? b0[idx] : (idx < NHEAD ? CB[idx - 20000] : 0.f);
    for (int idx = i; idx < V3PAD; idx += stride)
        g_b3p[idx] = (idx < 67735) ? b3[idx] : 0.f;
}

// ---------------- 1) projections (8-token tiles) ----------------
__global__ void __launch_bounds__(512)
k_proj(const float* __restrict__ hidden,
       const float* __restrict__ p0, const float* __restrict__ p1,
       const float* __restrict__ p2, const float* __restrict__ p3) {
    __shared__ float h[8][512];
    int t0 = blockIdx.x * 8;
    int tid = threadIdx.x;
    for (int i = tid; i < 8 * 512; i += 512)
        h[i >> 9][i & 511] = hidden[(t0 + (i >> 9)) * 512 + (i & 511)];
    __syncthreads();
    {
        int j = tid;
        float a[8];
#pragma unroll
        for (int i = 0; i < 8; i++) a[i] = 0.f;
#pragma unroll 4
        for (int k = 0; k < 512; k++) {
            float w = p0[k * 512 + j];
#pragma unroll
            for (int i = 0; i < 8; i++) a[i] = fmaf(h[i][k], w, a[i]);
        }
#pragma unroll
        for (int i = 0; i < 8; i++) g_hp0[(t0 + i) * 512 + j] = a[i];
    }
    if (tid < 128) {
        int j = tid;
        float a[8];
#pragma unroll
        for (int i = 0; i < 8; i++) a[i] = 0.f;
#pragma unroll 4
        for (int k = 0; k < 512; k++) {
            float w = p1[k * 128 + j];
#pragma unroll
            for (int i = 0; i < 8; i++) a[i] = fmaf(h[i][k], w, a[i]);
        }
#pragma unroll
        for (int i = 0; i < 8; i++) g_hp1[(t0 + i) * 128 + j] = a[i];
    }
    if (tid < 32) {
        int j = tid;
        float a[8];
#pragma unroll
        for (int i = 0; i < 8; i++) a[i] = 0.f;
#pragma unroll 4
        for (int k = 0; k < 512; k++) {
            float w = p2[k * 32 + j];
#pragma unroll
            for (int i = 0; i < 8; i++) a[i] = fmaf(h[i][k], w, a[i]);
        }
#pragma unroll
        for (int i = 0; i < 8; i++) g_hp2[(t0 + i) * 32 + j] = a[i];
    }
    if (tid < 8) {
        int j = tid;
        float a[8];
#pragma unroll
        for (int i = 0; i < 8; i++) a[i] = 0.f;
#pragma unroll 4
        for (int k = 0; k < 512; k++) {
            float w = p3[k * 8 + j];
#pragma unroll
            for (int i = 0; i < 8; i++) a[i] = fmaf(h[i][k], w, a[i]);
        }
#pragma unroll
        for (int i = 0; i < 8; i++) g_hp3[(t0 + i) * 8 + j] = a[i];
    }
}

// ---------------- 2) cluster-id + compaction ----------------
__global__ void k_compact(const int* __restrict__ target) {
    int t = threadIdx.x;
    if (t < 3) g_cnt[t] = 0;
    __syncthreads();
    int tg = target[t];
    int cid = (tg >= 20000) + (tg >= 40000) + (tg >= 200000);
    if (cid > 0) {
        int p = atomicAdd(&g_cnt[cid - 1], 1);
        g_list[cid - 1][p] = t;
        g_pos[t] = p;
    } else {
        g_pos[t] = -1;
    }
}

// ---------------- 3) head: 64-token tiles, 32 rows/block, k-chunked ----------
__global__ void __launch_bounds__(128, 4)
k_head(const int* __restrict__ target) {
    __shared__ unsigned long long shp[64][65];   // [k-pair][token], 33 KB
    __shared__ float red[4][64];
    int tile = blockIdx.x, chunk = blockIdx.y;
    int tid = threadIdx.x, warp = tid >> 5, lane = tid & 31;
    int t0 = tile * 64;
    int row0 = chunk * 32 + warp * 8;

    unsigned long long acc[8][2];
#pragma unroll
    for (int i = 0; i < 8; i++) { acc[i][0] = 0ull; acc[i][1] = 0ull; }

    for (int kc = 0; kc < 4; kc++) {
        __syncthreads();
        int kb = kc * 128 + tid;
#pragma unroll 4
        for (int tok = 0; tok < 64; tok++) {
            float v = g_hp0[(t0 + tok) * 512 + kb];
            ((float*)&shp[tid >> 1][tok])[tid & 1] = v;
        }
        __syncthreads();
        const float* wp = g_headW + (size_t)row0 * 512 + kc * 128;
#pragma unroll 2
        for (int k = 0; k < 128; k += 4) {
            int kp = k >> 1;
            unsigned long long a0 = shp[kp][lane];
            unsigned long long a1 = shp[kp][lane + 32];
            unsigned long long c0 = shp[kp + 1][lane];
            unsigned long long c1 = shp[kp + 1][lane + 32];
#pragma unroll
            for (int i = 0; i < 8; i++) {
                ulonglong2 w = *(const ulonglong2*)(wp + i * 512 + k);
                acc[i][0] = ffma2(a0, w.x, acc[i][0]);
                acc[i][0] = ffma2(c0, w.y, acc[i][0]);
                acc[i][1] = ffma2(a1, w.x, acc[i][1]);
                acc[i][1] = ffma2(c1, w.y, acc[i][1]);
            }
        }
    }
    // epilogue
    int tok0 = t0 + lane, tok1 = t0 + lane + 32;
    int tg0 = target[tok0], tg1 = target[tok1];
    int cid0 = (tg0 >= 20000) + (tg0 >= 40000) + (tg0 >= 200000);
    int cid1 = (tg1 >= 20000) + (tg1 >= 40000) + (tg1 >= 200000);
    int nc0 = cid0 ? (NHEAD - cid0) : tg0;
    int nc1 = cid1 ? (NHEAD - cid1) : tg1;
    float s0 = 0.f, s1 = 0.f;
#pragma unroll
    for (int i = 0; i < 8; i++) {
        int row = row0 + i;
        float bb = g_headB[row];
        float d0 = f2lo(acc[i][0]) + f2hi(acc[i][0]) + bb;
        float d1 = f2lo(acc[i][1]) + f2hi(acc[i][1]) + bb;
        if (row < NHEAD) { s0 += __expf(d0); s1 += __expf(d1); }
        if (row == nc0) g_nh[tok0] = d0;
        if (row == nc1) g_nh[tok1] = d1;
    }
    red[warp][lane] = s0;
    red[warp][lane + 32] = s1;
    __syncthreads();
    if (warp == 0) {
        float ta = red[0][lane] + red[1][lane] + red[2][lane] + red[3][lane];
        float tb = red[0][lane + 32] + red[1][lane + 32] + red[2][lane + 32] + red[3][lane + 32];
        g_ph[(size_t)tok0 * HCHUNKS + chunk] = ta;
        g_ph[(size_t)tok1 * HCHUNKS + chunk] = tb;
    }
}

// ---------------- 4) tails: compacted tokens, same loop shape ----------------
template <int E, int ROWS, int NCH, int CID, int OCC>
__global__ void __launch_bounds__(128, OCC)
k_tail(const float* __restrict__ Wa, const float* __restrict__ ba,
       const int* __restrict__ target) {
    constexpr int CROWS = 4 * ROWS;
    constexpr int KP = E / 2;
    __shared__ unsigned long long shp[KP][65];
    __shared__ float red[4][64];
    constexpr int c = CID - 1;
    const float* hp = (E == 128) ? g_hp1 : (E == 32) ? g_hp2 : g_hp3;
    const float* W = (CID == 3) ? g_W3p : Wa;
    const float* bias = (CID == 3) ? g_b3p : ba;
    float* gpt = (CID == 1) ? g_pt1 : (CID == 2) ? g_pt2 : g_pt3;
    constexpr int V = (CID == 1) ? 20000 : (CID == 2) ? 160000 : 67735;
    constexpr int L = (CID == 1) ? 20000 : (CID == 2) ? 40000 : 200000;

    int cnt = g_cnt[c];
    int tile = blockIdx.x;
    if (tile * 64 >= cnt) return;
    int chunk = blockIdx.y;
    int tid = threadIdx.x, warp = tid >> 5, lane = tid & 31;
    int row0 = chunk * CROWS + warp * ROWS;

    // stage 64 tokens of hp into [k-pair][token] layout
    {
        constexpr int WTOK = 128 / E;
        int tok_sub = tid / E;
        int k = tid % E;
#pragma unroll
        for (int base = 0; base < 64; base += WTOK) {
            int tok = base + tok_sub;
            int slot = tile * 64 + tok;
            int token = g_list[c][slot < cnt ? slot : cnt - 1];
            float v = hp[token * E + k];
            ((float*)&shp[k >> 1][tok])[k & 1] = v;
        }
    }
    __syncthreads();

    unsigned long long acc[ROWS][2];
#pragma unroll
    for (int i = 0; i < ROWS; i++) { acc[i][0] = 0ull; acc[i][1] = 0ull; }
    const float* wp = W + (size_t)row0 * E;
#pragma unroll 2
    for (int k = 0; k < E; k += 4) {
        int kp = k >> 1;
        unsigned long long a0 = shp[kp][lane];
        unsigned long long a1 = shp[kp][lane + 32];
        unsigned long long c0 = shp[kp + 1][lane];
        unsigned long long c1 = shp[kp + 1][lane + 32];
#pragma unroll
        for (int i = 0; i < ROWS; i++) {
            ulonglong2 w = *(const ulonglong2*)(wp + i * E + k);
            acc[i][0] = ffma2(a0, w.x, acc[i][0]);
            acc[i][0] = ffma2(c0, w.y, acc[i][0]);
            acc[i][1] = ffma2(a1, w.x, acc[i][1]);
            acc[i][1] = ffma2(c1, w.y, acc[i][1]);
        }
    }

    int slot0 = tile * 64 + lane, slot1 = slot0 + 32;
    int token0 = g_list[c][slot0 < cnt ? slot0 : cnt - 1];
    int token1 = g_list[c][slot1 < cnt ? slot1 : cnt - 1];
    int rel0 = target[token0] - L;
    int rel1 = target[token1] - L;
    float s0 = 0.f, s1 = 0.f;
#pragma unroll
    for (int i = 0; i < ROWS; i++) {
        int row = row0 + i;
        float bb = bias[row];
        float d0 = f2lo(acc[i][0]) + f2hi(acc[i][0]) + bb;
        float d1 = f2lo(acc[i][1]) + f2hi(acc[i][1]) + bb;
        if (row < V) { s0 += __expf(d0); s1 += __expf(d1); }
        if (row == rel0) g_nt[token0] = d0;
        if (row == rel1) g_nt[token1] = d1;
    }
    red[warp][lane] = s0;
    red[warp][lane + 32] = s1;
    __syncthreads();
    if (warp == 0) {
        float ta = red[0][lane] + red[1][lane] + red[2][lane] + red[3][lane];
        float tb = red[0][lane + 32] + red[1][lane + 32] + red[2][lane + 32] + red[3][lane + 32];
        gpt[(size_t)slot0 * NCH + chunk] = ta;
        gpt[(size_t)slot1 * NCH + chunk] = tb;
    }
}

// ---------------- 5) combine: warp per token ----------------
__global__ void k_comb(const int* __restrict__ target, float* __restrict__ out) {
    int t = (blockIdx.x * blockDim.x + threadIdx.x) >> 5;
    int lane = threadIdx.x & 31;
    if (t >= NTOK) return;
    float s = 0.f;
    for (int ch = lane; ch < HCHUNKS; ch += 32) s += g_ph[(size_t)t * HCHUNKS + ch];
#pragma unroll
    for (int o = 16; o; o >>= 1) s += __shfl_xor_sync(0xffffffffu, s, o);
    float hl = g_nh[t] - logf(s);
    int tg = target[t];
    int cid = (tg >= 20000) + (tg >= 40000) + (tg >= 200000);
    float nll = -hl;
    if (cid) {
        int p = g_pos[t];
        const float* pt;
        int nch;
        if (cid == 1) { pt = g_pt1 + (size_t)p * NCH1; nch = NCH1; }
        else if (cid == 2) { pt = g_pt2 + (size_t)p * NCH2; nch = NCH2; }
        else { pt = g_pt3 + (size_t)p * NCH3; nch = NCH3; }
        float st = 0.f;
        for (int ch = lane; ch < nch; ch += 32) st += pt[ch];
#pragma unroll
        for (int o = 16; o; o >>= 1) st += __shfl_xor_sync(0xffffffffu, st, o);
        nll = -(hl + g_nt[t] - logf(st));
    }
    if (lane == 0) out[t] = nll;
}

// ---------------- launch ----------------
extern "C" void kernel_launch(void* const* d_in, const int* in_sizes, int n_in,
                              void* d_out, int out_size) {
    const float* hidden = (const float*)d_in[0];
    const int*   target = (const int*)d_in[1];
    const float* W0 = (const float*)d_in[2];
    const float* b0 = (const float*)d_in[3];
    const float* p0 = (const float*)d_in[4];
    const float* W1 = (const float*)d_in[5];
    const float* b1 = (const float*)d_in[6];
    const float* p1 = (const float*)d_in[7];
    const float* W2 = (const float*)d_in[8];
    const float* b2 = (const float*)d_in[9];
    const float* p2 = (const float*)d_in[10];
    const float* W3 = (const float*)d_in[11];
    const float* b3 = (const float*)d_in[12];
    const float* p3 = (const float*)d_in[13];
    const float* CW = (const float*)d_in[14];
    const float* CB = (const float*)d_in[15];

    k_prep<<<2048, 256>>>((const float4*)W0, b0, (const float4*)CW, CB,
                          (const float4*)W3, b3);
    k_proj<<<NTOK / 8, 512>>>(hidden, p0, p1, p2, p3);
    k_compact<<<1, NTOK>>>(target);
    k_head<<<dim3(16, HCHUNKS), 128>>>(target);
    k_tail<128, 8,  NCH1, 1, 4><<<dim3(TILES1, NCH1), 128>>>(W1, b1, target);
    k_tail<32,  16, NCH2, 2, 3><<<dim3(TILES2, NCH2), 128>>>(W2, b2, target);
    k_tail<8,   8,  NCH3, 3, 4><<<dim3(TILES3, NCH3), 128>>>(W3, b3, target);
    k_comb<<<128, 256>>>(target, (float*)d_out);
}